// round 15
// baseline (speedup 1.0000x reference)
#include <cuda_runtime.h>
#include <cuda_fp16.h>
#include <cstdint>

#define NN 100000
#define NE 1600000
#define CIN 128
#define NBLK ((NN + 255) / 256)   // 391 scan blocks

// ---------------- scratch ---------------------------------------------------
static __device__ int    g_deg[NN];
static __device__ int    g_cur[NN];
static __device__ float  g_dis[NN];
static __device__ int    g_off[NN + 1];
static __device__ int    g_bsum[512];
static __device__ int    g_bscan[512];
static __device__ int    g_ep[NE];                 // src per (dst-sorted) edge
static __device__ __half g_h[(size_t)NN * 128];    // dis-scaled messages (fp16)
static __device__ __half g_a[(size_t)NN * 128];    // relu(agg+b) layer input (fp16)
// pre-transposed + fp16 hi/lo split weights: [COUT][CIN]
static __device__ __half g_w1h[128 * 128], g_w1l[128 * 128];
static __device__ __half g_w2h[128 * 128], g_w2l[128 * 128];
static __device__ __half g_w3h[64 * 128],  g_w3l[64 * 128];

// ---------------- PTX helpers ------------------------------------------------
__device__ __forceinline__ void ldsm4(uint32_t* r, uint32_t addr) {
    asm volatile("ldmatrix.sync.aligned.m8n8.x4.shared.b16 {%0,%1,%2,%3}, [%4];"
                 : "=r"(r[0]), "=r"(r[1]), "=r"(r[2]), "=r"(r[3]) : "r"(addr));
}
__device__ __forceinline__ uint32_t smem_u32(const void* p) {
    uint32_t a;
    asm("{ .reg .u64 t; cvta.to.shared.u64 t, %1; cvt.u32.u64 %0, t; }" : "=r"(a) : "l"(p));
    return a;
}
__device__ __forceinline__ void mma16816(float* d, const uint32_t* a,
                                         uint32_t b0, uint32_t b1) {
    asm volatile(
        "mma.sync.aligned.m16n8k16.row.col.f32.f16.f16.f32 "
        "{%0,%1,%2,%3}, {%4,%5,%6,%7}, {%8,%9}, {%0,%1,%2,%3};"
        : "+f"(d[0]), "+f"(d[1]), "+f"(d[2]), "+f"(d[3])
        : "r"(a[0]), "r"(a[1]), "r"(a[2]), "r"(a[3]), "r"(b0), "r"(b1));
}
__device__ __forceinline__ float4 h4_to_f4(uint2 u) {
    float2 a = __half22float2(*reinterpret_cast<__half2*>(&u.x));
    float2 b = __half22float2(*reinterpret_cast<__half2*>(&u.y));
    return make_float4(a.x, a.y, b.x, b.y);
}

// ---------------- init: self-loop degree + weight transpose/split ------------
__global__ void k_init(const float* __restrict__ W1, const float* __restrict__ W2,
                       const float* __restrict__ W3) {
    int i = blockIdx.x * blockDim.x + threadIdx.x;
    if (i < NN) g_deg[i] = 1;                       // self loop
    if (i < 16384) {
        int k = i >> 7, n = i & 127;
        float v = W1[i];
        __half hi = __float2half_rn(v);
        g_w1h[n * 128 + k] = hi;
        g_w1l[n * 128 + k] = __float2half_rn(v - __half2float(hi));
        v = W2[i]; hi = __float2half_rn(v);
        g_w2h[n * 128 + k] = hi;
        g_w2l[n * 128 + k] = __float2half_rn(v - __half2float(hi));
    }
    if (i < 8192) {
        int k = i >> 6, n = i & 63;
        float v = W3[i];
        __half hi = __float2half_rn(v);
        g_w3h[n * 128 + k] = hi;
        g_w3l[n * 128 + k] = __float2half_rn(v - __half2float(hi));
    }
}
__global__ void k_deg_count(const int* __restrict__ dst) {
    int e = blockIdx.x * blockDim.x + threadIdx.x;
    if (e < NE) atomicAdd(&g_deg[dst[e]], 1);
}

// ---------------- CSR build (dis fused into scan1) ---------------------------
__global__ void k_scan1() {
    __shared__ int s[256];
    int t = threadIdx.x;
    int i = blockIdx.x * 256 + t;
    int deg = (i < NN) ? g_deg[i] : 1;
    if (i < NN) g_dis[i] = rsqrtf((float)deg);
    int v = (i < NN) ? (deg - 1) : 0;
    s[t] = v; __syncthreads();
#pragma unroll
    for (int off = 1; off < 256; off <<= 1) {
        int a = (t >= off) ? s[t - off] : 0;
        __syncthreads();
        s[t] += a; __syncthreads();
    }
    if (i < NN) g_off[i] = s[t] - v;
    if (t == 255) g_bsum[blockIdx.x] = s[255];
}
__global__ void k_scan2() {
    __shared__ int s[512];
    int t = threadIdx.x;
    int v = (t < NBLK) ? g_bsum[t] : 0;
    s[t] = v; __syncthreads();
#pragma unroll
    for (int off = 1; off < 512; off <<= 1) {
        int a = (t >= off) ? s[t - off] : 0;
        __syncthreads();
        s[t] += a; __syncthreads();
    }
    g_bscan[t] = s[t] - v;
}
__global__ void k_scan3() {
    int i = blockIdx.x * blockDim.x + threadIdx.x;
    if (i < NN) {
        int o = g_off[i] + g_bscan[i >> 8];
        g_off[i] = o;
        g_cur[i] = o;
    }
    if (i == 0) g_off[NN] = NE;
}
__global__ void k_fill(const int* __restrict__ src, const int* __restrict__ dst) {
    int e = blockIdx.x * blockDim.x + threadIdx.x;
    if (e >= NE) return;
    int pos = atomicAdd(&g_cur[dst[e]], 1);
    g_ep[pos] = src[e];
}

// ---------------- scale layer-1 messages: h *= dis[row] (in place) -----------
__global__ void k_scale() {
    int idx = blockIdx.x * blockDim.x + threadIdx.x;     // uint2 = 4 halves
    if (idx >= NN * 32) return;
    int row = idx >> 5;
    float dd = g_dis[row];
    uint2* hp = reinterpret_cast<uint2*>(g_h);
    float4 v = h4_to_f4(hp[idx]);
    __half2 o0 = __floats2half2_rn(v.x * dd, v.y * dd);
    __half2 o1 = __floats2half2_rn(v.z * dd, v.w * dd);
    uint2 o;
    o.x = *reinterpret_cast<uint32_t*>(&o0);
    o.y = *reinterpret_cast<uint32_t*>(&o1);
    hp[idx] = o;
}

// ---------------- fp16 tensor-core GEMM: 2 MMAs (A * (wh + wl)) --------------
// A is fp16 in smem: copied directly (HALF_IN) or converted fp32->fp16.
// HALF_IN epilogue scales by dis; fp32-input (layer 1) stores UNscaled
// (dis applied later by k_scale, so gemm1 has no CSR dependency).
template <int COUT, bool HALF_IN>
__global__ void __launch_bounds__(256, 2)
k_gemm_mma(const void* __restrict__ in_, const __half* __restrict__ wh,
           const __half* __restrict__ wl, __half* __restrict__ h)
{
    constexpr int PITCH = 144;                 // bytes per smem row (72 halves)
    constexpr int ASZ = 128 * PITCH;           // 18432
    constexpr int BSZ = COUT * PITCH;
    constexpr int NTW = COUT / 16;

    extern __shared__ char smem[];
    char* A0 = smem;
    char* Bh = smem + ASZ;
    char* Bl = Bh + BSZ;
    uint32_t sb = smem_u32(smem);

    int tid = threadIdx.x;
    int wid = tid >> 5, lane = tid & 31;
    int wm = wid >> 1, wn = wid & 1;
    int row0 = blockIdx.x * 128;

    float acc[2][NTW][4];
#pragma unroll
    for (int f = 0; f < 2; f++)
#pragma unroll
        for (int t = 0; t < NTW; t++)
#pragma unroll
            for (int q = 0; q < 4; q++) acc[f][t][q] = 0.f;

    uint32_t lrow = lane & 7, quad = lane >> 3;
    uint32_t aoff = sb +
                    (wm * 32 + lrow + ((quad & 1) << 3)) * PITCH + ((quad & 2) << 3);
    uint32_t boff = sb + (uint32_t)ASZ +
                    (wn * (COUT / 2) + lrow + ((quad & 2) << 2)) * PITCH + ((quad & 1) << 4);

    for (int c = 0; c < 2; c++) {
        // ---- stage A chunk [128 x 64] --------------------------------------
        {
            int r = tid >> 1, half = tid & 1;
            int gr = row0 + r;
            if (HALF_IN) {
                const uint4* ip = reinterpret_cast<const uint4*>(
                    (const __half*)in_ + (size_t)gr * CIN + c * 64 + half * 32);
                uint4* ar = reinterpret_cast<uint4*>(A0 + r * PITCH + half * 64);
                if (gr < NN) {
#pragma unroll
                    for (int q = 0; q < 4; q++) ar[q] = ip[q];
                } else {
                    uint4 z = make_uint4(0, 0, 0, 0);
#pragma unroll
                    for (int q = 0; q < 4; q++) ar[q] = z;
                }
            } else {
                const float* ip = (const float*)in_ + (size_t)gr * CIN + c * 64 + half * 32;
                __half2* ar = reinterpret_cast<__half2*>(A0 + r * PITCH + half * 64);
#pragma unroll
                for (int q = 0; q < 8; q++) {
                    float4 v = make_float4(0.f, 0.f, 0.f, 0.f);
                    if (gr < NN) v = *reinterpret_cast<const float4*>(ip + q * 4);
                    ar[q * 2]     = __floats2half2_rn(v.x, v.y);
                    ar[q * 2 + 1] = __floats2half2_rn(v.z, v.w);
                }
            }
        }
        // ---- stage B chunk [COUT x 64] fp16 copy ---------------------------
        {
            constexpr int TPR = 256 / COUT;
            constexpr int VPT = 8 / TPR;
            int n = tid / TPR, part = tid % TPR;
            const uint4* sh = reinterpret_cast<const uint4*>(wh + n * 128 + c * 64) + part * VPT;
            const uint4* sl = reinterpret_cast<const uint4*>(wl + n * 128 + c * 64) + part * VPT;
            uint4* dh = reinterpret_cast<uint4*>(Bh + n * PITCH) + part * VPT;
            uint4* dl = reinterpret_cast<uint4*>(Bl + n * PITCH) + part * VPT;
#pragma unroll
            for (int v = 0; v < VPT; v++) { dh[v] = sh[v]; dl[v] = sl[v]; }
        }
        __syncthreads();

        // ---- compute: 4 k16 steps, 2 MMAs per n8-pair ----------------------
#pragma unroll
        for (int kk = 0; kk < 4; kk++) {
            uint32_t ka = (uint32_t)(kk << 5);
            uint32_t afr[2][4];
            ldsm4(afr[0], aoff + ka);
            ldsm4(afr[1], aoff + 16 * PITCH + ka);
#pragma unroll
            for (int tp = 0; tp < NTW / 2; tp++) {
                uint32_t bfr[4], bfl[4];
                ldsm4(bfr, boff + tp * 16 * PITCH + ka);
                ldsm4(bfl, boff + BSZ + tp * 16 * PITCH + ka);
#pragma unroll
                for (int f = 0; f < 2; f++) {
                    mma16816(acc[f][2 * tp],     afr[f], bfr[0], bfr[1]);
                    mma16816(acc[f][2 * tp],     afr[f], bfl[0], bfl[1]);
                    mma16816(acc[f][2 * tp + 1], afr[f], bfr[2], bfr[3]);
                    mma16816(acc[f][2 * tp + 1], afr[f], bfl[2], bfl[3]);
                }
            }
        }
        __syncthreads();
    }

    // ---- epilogue -----------------------------------------------------------
#pragma unroll
    for (int f = 0; f < 2; f++) {
        int r0g = row0 + wm * 32 + f * 16 + (lane >> 2);
        float ds0 = 1.f, ds1 = 1.f;
        if (HALF_IN) {
            ds0 = (r0g < NN) ? g_dis[r0g] : 0.f;
            ds1 = (r0g + 8 < NN) ? g_dis[r0g + 8] : 0.f;
        }
#pragma unroll
        for (int t = 0; t < NTW; t++) {
            int ncol = wn * (COUT / 2) + t * 8 + ((lane & 3) << 1);
            if (r0g < NN) {
                __half2 o = __floats2half2_rn(acc[f][t][0] * ds0, acc[f][t][1] * ds0);
                *reinterpret_cast<__half2*>(h + (size_t)r0g * COUT + ncol) = o;
            }
            if (r0g + 8 < NN) {
                __half2 o = __floats2half2_rn(acc[f][t][2] * ds1, acc[f][t][3] * ds1);
                *reinterpret_cast<__half2*>(h + (size_t)(r0g + 8) * COUT + ncol) = o;
            }
        }
    }
}

// --------- gather (layers 1,2): nxt = fp16(relu(dd*(Σ h'[s] + h'[d]) + b)) ---
__global__ void k_gather128(const __half* __restrict__ h, const float* __restrict__ bias,
                            __half* __restrict__ nxt)
{
    int warp = (blockIdx.x * blockDim.x + threadIdx.x) >> 5;
    int lane = threadIdx.x & 31;
    if (warp >= NN) return;
    int beg = g_off[warp], end = g_off[warp + 1];
    const uint2* hp = reinterpret_cast<const uint2*>(h);
    float4 acc = h4_to_f4(hp[warp * 32 + lane]);       // self term
    int i = beg;
    for (; i + 4 <= end; i += 4) {
        float4 v0 = h4_to_f4(hp[g_ep[i    ] * 32 + lane]);
        float4 v1 = h4_to_f4(hp[g_ep[i + 1] * 32 + lane]);
        float4 v2 = h4_to_f4(hp[g_ep[i + 2] * 32 + lane]);
        float4 v3 = h4_to_f4(hp[g_ep[i + 3] * 32 + lane]);
        acc.x += (v0.x + v1.x) + (v2.x + v3.x);
        acc.y += (v0.y + v1.y) + (v2.y + v3.y);
        acc.z += (v0.z + v1.z) + (v2.z + v3.z);
        acc.w += (v0.w + v1.w) + (v2.w + v3.w);
    }
    for (; i < end; i++) {
        float4 v = h4_to_f4(hp[g_ep[i] * 32 + lane]);
        acc.x += v.x; acc.y += v.y; acc.z += v.z; acc.w += v.w;
    }
    float dd = g_dis[warp];
    float4 b = reinterpret_cast<const float4*>(bias)[lane];
    float rx = fmaxf(fmaf(acc.x, dd, b.x), 0.f);
    float ry = fmaxf(fmaf(acc.y, dd, b.y), 0.f);
    float rz = fmaxf(fmaf(acc.z, dd, b.z), 0.f);
    float rw = fmaxf(fmaf(acc.w, dd, b.w), 0.f);
    uint2 o;
    __half2 o0 = __floats2half2_rn(rx, ry);
    __half2 o1 = __floats2half2_rn(rz, rw);
    o.x = *reinterpret_cast<uint32_t*>(&o0);
    o.y = *reinterpret_cast<uint32_t*>(&o1);
    reinterpret_cast<uint2*>(nxt)[warp * 32 + lane] = o;
}

// final layer: COUT=64, fused +b3, fp32 straight to out
__global__ void k_gather64f(const __half* __restrict__ h, const float* __restrict__ b3,
                            float* __restrict__ out)
{
    int warp = (blockIdx.x * blockDim.x + threadIdx.x) >> 5;
    int lane = threadIdx.x & 31;
    if (warp >= NN) return;
    int beg = g_off[warp], end = g_off[warp + 1];
    const uint32_t* hp = reinterpret_cast<const uint32_t*>(h);
    uint32_t su = hp[warp * 32 + lane];
    float2 acc = __half22float2(*reinterpret_cast<__half2*>(&su));  // self term
    int i = beg;
    for (; i + 4 <= end; i += 4) {
        uint32_t u0 = hp[g_ep[i    ] * 32 + lane];
        uint32_t u1 = hp[g_ep[i + 1] * 32 + lane];
        uint32_t u2 = hp[g_ep[i + 2] * 32 + lane];
        uint32_t u3 = hp[g_ep[i + 3] * 32 + lane];
        float2 v0 = __half22float2(*reinterpret_cast<__half2*>(&u0));
        float2 v1 = __half22float2(*reinterpret_cast<__half2*>(&u1));
        float2 v2 = __half22float2(*reinterpret_cast<__half2*>(&u2));
        float2 v3 = __half22float2(*reinterpret_cast<__half2*>(&u3));
        acc.x += (v0.x + v1.x) + (v2.x + v3.x);
        acc.y += (v0.y + v1.y) + (v2.y + v3.y);
    }
    for (; i < end; i++) {
        uint32_t u = hp[g_ep[i] * 32 + lane];
        float2 v = __half22float2(*reinterpret_cast<__half2*>(&u));
        acc.x += v.x; acc.y += v.y;
    }
    float dd = g_dis[warp];
    float2 b = reinterpret_cast<const float2*>(b3)[lane];
    float2 r;
    r.x = fmaf(acc.x, dd, b.x);
    r.y = fmaf(acc.y, dd, b.y);
    reinterpret_cast<float2*>(out)[warp * 32 + lane] = r;
}

// ---------------- launcher ---------------------------------------------------
extern "C" void kernel_launch(void* const* d_in, const int* in_sizes, int n_in,
                              void* d_out, int out_size)
{
    const float* x  = (const float*)d_in[0];
    const int*   ei = (const int*)d_in[1];
    const float* W1 = (const float*)d_in[2];
    const float* b1 = (const float*)d_in[3];
    const float* W2 = (const float*)d_in[4];
    const float* b2 = (const float*)d_in[5];
    const float* W3 = (const float*)d_in[6];
    const float* b3 = (const float*)d_in[7];
    float* out = (float*)d_out;

    const int* src = ei;            // edge_index[0]
    const int* dst = ei + NE;       // edge_index[1]

    __half *ph = nullptr, *pa = nullptr;
    cudaGetSymbolAddress((void**)&ph, g_h);
    cudaGetSymbolAddress((void**)&pa, g_a);
    __half *w1h, *w1l, *w2h, *w2l, *w3h, *w3l;
    cudaGetSymbolAddress((void**)&w1h, g_w1h);
    cudaGetSymbolAddress((void**)&w1l, g_w1l);
    cudaGetSymbolAddress((void**)&w2h, g_w2h);
    cudaGetSymbolAddress((void**)&w2l, g_w2l);
    cudaGetSymbolAddress((void**)&w3h, g_w3h);
    cudaGetSymbolAddress((void**)&w3l, g_w3l);

    const int smemL1 = 1 * 128 * 144 + 2 * 128 * 144;   // 55296 (single fp16 A)
    const int smemL2 = 1 * 128 * 144 + 2 * 128 * 144;   // 55296
    const int smemL3 = 1 * 128 * 144 + 2 * 64 * 144;    // 36864
    cudaFuncSetAttribute(k_gemm_mma<128, false>, cudaFuncAttributeMaxDynamicSharedMemorySize, smemL1);
    cudaFuncSetAttribute(k_gemm_mma<128, true>,  cudaFuncAttributeMaxDynamicSharedMemorySize, smemL2);
    cudaFuncSetAttribute(k_gemm_mma<64,  true>,  cudaFuncAttributeMaxDynamicSharedMemorySize, smemL3);

    const int gB = (NN + 127) / 128;         // 782 M-tiles
    const int gG = (NN * 32 + 255) / 256;    // warp per node

    // fork machinery (host objects only; safe during stream capture)
    cudaStream_t s2;
    cudaStreamCreateWithFlags(&s2, cudaStreamNonBlocking);
    cudaEvent_t eFork, eDis, eJoin;
    cudaEventCreateWithFlags(&eFork, cudaEventDisableTiming);
    cudaEventCreateWithFlags(&eDis,  cudaEventDisableTiming);
    cudaEventCreateWithFlags(&eJoin, cudaEventDisableTiming);

    // ---- setup root ----
    k_init<<<NBLK, 256>>>(W1, W2, W3);
    cudaEventRecord(eFork, 0);

    // ---- branch A (side stream): layer-1 GEMM (weights only) ----
    cudaStreamWaitEvent(s2, eFork, 0);
    k_gemm_mma<128, false><<<gB, 256, smemL1, s2>>>(x, w1h, w1l, ph);

    // ---- branch B (main stream): degree + dis ----
    k_deg_count<<<(NE + 255) / 256, 256>>>(dst);
    k_scan1<<<NBLK, 256>>>();
    cudaEventRecord(eDis, 0);                       // dis ready

    // side stream: scale h1 by dis (hidden under scan2..fill)
    cudaStreamWaitEvent(s2, eDis, 0);
    k_scale<<<(NN * 32 + 255) / 256, 256, 0, s2>>>();
    cudaEventRecord(eJoin, s2);

    // main stream: finish CSR
    k_scan2<<<1, 512>>>();
    k_scan3<<<NBLK, 256>>>();
    k_fill<<<(NE + 255) / 256, 256>>>(src, dst);

    // ---- join, then serial layer chain (R12 topology) ----
    cudaStreamWaitEvent(0, eJoin, 0);
    k_gather128<<<gG, 256>>>(ph, b1, pa);
    k_gemm_mma<128, true><<<gB, 256, smemL2>>>(pa, w2h, w2l, ph);
    k_gather128<<<gG, 256>>>(ph, b2, pa);
    k_gemm_mma<64, true><<<gB, 256, smemL3>>>(pa, w3h, w3l, ph);
    k_gather64f<<<gG, 256>>>(ph, b3, out);
    // streams/events intentionally not destroyed (host objects; capture-safe)
}

// round 17
// speedup vs baseline: 1.4648x; 1.4648x over previous
#include <cuda_runtime.h>
#include <cuda_fp16.h>
#include <cstdint>

#define NN 100000
#define NE 1600000
#define CIN 128
#define NBLK ((NN + 255) / 256)   // 391 scan blocks

// ---------------- scratch ---------------------------------------------------
static __device__ int    g_deg[NN];
static __device__ int    g_cur[NN];
static __device__ float  g_dis[NN];
static __device__ int    g_off[NN + 1];
static __device__ int    g_bsum[512];
static __device__ int    g_bscan[512];
static __device__ int    g_ep[NE];                 // src per (dst-sorted) edge
static __device__ __half g_h[(size_t)NN * 128];    // dis-scaled messages (fp16)
static __device__ __half g_a[(size_t)NN * 128];    // relu(agg+b) layer input (fp16)
// pre-transposed + fp16 hi/lo split weights: [COUT][CIN]
static __device__ __half g_w1h[128 * 128], g_w1l[128 * 128];
static __device__ __half g_w2h[128 * 128], g_w2l[128 * 128];
static __device__ __half g_w3h[64 * 128],  g_w3l[64 * 128];

// ---------------- PTX helpers ------------------------------------------------
__device__ __forceinline__ void ldsm4(uint32_t* r, uint32_t addr) {
    asm volatile("ldmatrix.sync.aligned.m8n8.x4.shared.b16 {%0,%1,%2,%3}, [%4];"
                 : "=r"(r[0]), "=r"(r[1]), "=r"(r[2]), "=r"(r[3]) : "r"(addr));
}
__device__ __forceinline__ uint32_t smem_u32(const void* p) {
    uint32_t a;
    asm("{ .reg .u64 t; cvta.to.shared.u64 t, %1; cvt.u32.u64 %0, t; }" : "=r"(a) : "l"(p));
    return a;
}
__device__ __forceinline__ void mma16816(float* d, const uint32_t* a,
                                         uint32_t b0, uint32_t b1) {
    asm volatile(
        "mma.sync.aligned.m16n8k16.row.col.f32.f16.f16.f32 "
        "{%0,%1,%2,%3}, {%4,%5,%6,%7}, {%8,%9}, {%0,%1,%2,%3};"
        : "+f"(d[0]), "+f"(d[1]), "+f"(d[2]), "+f"(d[3])
        : "r"(a[0]), "r"(a[1]), "r"(a[2]), "r"(a[3]), "r"(b0), "r"(b1));
}
__device__ __forceinline__ float4 h4_to_f4(uint2 u) {
    float2 a = __half22float2(*reinterpret_cast<__half2*>(&u.x));
    float2 b = __half22float2(*reinterpret_cast<__half2*>(&u.y));
    return make_float4(a.x, a.y, b.x, b.y);
}

// ---------------- init: self-loop degree + weight transpose/split ------------
__global__ void k_init(const float* __restrict__ W1, const float* __restrict__ W2,
                       const float* __restrict__ W3) {
    int i = blockIdx.x * blockDim.x + threadIdx.x;
    if (i < NN) g_deg[i] = 1;                       // self loop
    if (i < 16384) {
        int k = i >> 7, n = i & 127;
        float v = W1[i];
        __half hi = __float2half_rn(v);
        g_w1h[n * 128 + k] = hi;
        g_w1l[n * 128 + k] = __float2half_rn(v - __half2float(hi));
        v = W2[i]; hi = __float2half_rn(v);
        g_w2h[n * 128 + k] = hi;
        g_w2l[n * 128 + k] = __float2half_rn(v - __half2float(hi));
    }
    if (i < 8192) {
        int k = i >> 6, n = i & 63;
        float v = W3[i];
        __half hi = __float2half_rn(v);
        g_w3h[n * 128 + k] = hi;
        g_w3l[n * 128 + k] = __float2half_rn(v - __half2float(hi));
    }
}
__global__ void k_deg_count(const int* __restrict__ dst) {
    int e = blockIdx.x * blockDim.x + threadIdx.x;
    if (e < NE) atomicAdd(&g_deg[dst[e]], 1);
}

// ---------------- CSR build (dis fused into scan1) ---------------------------
__global__ void k_scan1() {
    __shared__ int s[256];
    int t = threadIdx.x;
    int i = blockIdx.x * 256 + t;
    int deg = (i < NN) ? g_deg[i] : 1;
    if (i < NN) g_dis[i] = rsqrtf((float)deg);
    int v = (i < NN) ? (deg - 1) : 0;
    s[t] = v; __syncthreads();
#pragma unroll
    for (int off = 1; off < 256; off <<= 1) {
        int a = (t >= off) ? s[t - off] : 0;
        __syncthreads();
        s[t] += a; __syncthreads();
    }
    if (i < NN) g_off[i] = s[t] - v;
    if (t == 255) g_bsum[blockIdx.x] = s[255];
}
__global__ void k_scan2() {
    __shared__ int s[512];
    int t = threadIdx.x;
    int v = (t < NBLK) ? g_bsum[t] : 0;
    s[t] = v; __syncthreads();
#pragma unroll
    for (int off = 1; off < 512; off <<= 1) {
        int a = (t >= off) ? s[t - off] : 0;
        __syncthreads();
        s[t] += a; __syncthreads();
    }
    g_bscan[t] = s[t] - v;
}
__global__ void k_scan3() {
    int i = blockIdx.x * blockDim.x + threadIdx.x;
    if (i < NN) {
        int o = g_off[i] + g_bscan[i >> 8];
        g_off[i] = o;
        g_cur[i] = o;
    }
    if (i == 0) g_off[NN] = NE;
}
__global__ void k_fill(const int* __restrict__ src, const int* __restrict__ dst) {
    int e = blockIdx.x * blockDim.x + threadIdx.x;
    if (e >= NE) return;
    int pos = atomicAdd(&g_cur[dst[e]], 1);
    g_ep[pos] = src[e];
}

// ---------------- scale layer-1 messages: h *= dis[row] (in place) -----------
__global__ void k_scale() {
    int idx = blockIdx.x * blockDim.x + threadIdx.x;     // uint2 = 4 halves
    if (idx >= NN * 32) return;
    int row = idx >> 5;
    float dd = g_dis[row];
    uint2* hp = reinterpret_cast<uint2*>(g_h);
    float4 v = h4_to_f4(hp[idx]);
    __half2 o0 = __floats2half2_rn(v.x * dd, v.y * dd);
    __half2 o1 = __floats2half2_rn(v.z * dd, v.w * dd);
    uint2 o;
    o.x = *reinterpret_cast<uint32_t*>(&o0);
    o.y = *reinterpret_cast<uint32_t*>(&o1);
    hp[idx] = o;
}

// ---------------- fp16 tensor-core GEMM: 2 MMAs (A * (wh + wl)) --------------
// A is fp16 in smem: copied directly (HALF_IN) or converted fp32->fp16.
// HALF_IN epilogue scales by dis; fp32-input (layer 1) stores UNscaled
// (dis applied later by k_scale, so gemm1 has no CSR dependency).
template <int COUT, bool HALF_IN>
__global__ void __launch_bounds__(256, 2)
k_gemm_mma(const void* __restrict__ in_, const __half* __restrict__ wh,
           const __half* __restrict__ wl, __half* __restrict__ h)
{
    constexpr int PITCH = 144;                 // bytes per smem row (72 halves)
    constexpr int ASZ = 128 * PITCH;           // 18432
    constexpr int BSZ = COUT * PITCH;
    constexpr int NTW = COUT / 16;

    extern __shared__ char smem[];
    char* A0 = smem;
    char* Bh = smem + ASZ;
    char* Bl = Bh + BSZ;
    uint32_t sb = smem_u32(smem);

    int tid = threadIdx.x;
    int wid = tid >> 5, lane = tid & 31;
    int wm = wid >> 1, wn = wid & 1;
    int row0 = blockIdx.x * 128;

    float acc[2][NTW][4];
#pragma unroll
    for (int f = 0; f < 2; f++)
#pragma unroll
        for (int t = 0; t < NTW; t++)
#pragma unroll
            for (int q = 0; q < 4; q++) acc[f][t][q] = 0.f;

    uint32_t lrow = lane & 7, quad = lane >> 3;
    uint32_t aoff = sb +
                    (wm * 32 + lrow + ((quad & 1) << 3)) * PITCH + ((quad & 2) << 3);
    uint32_t boff = sb + (uint32_t)ASZ +
                    (wn * (COUT / 2) + lrow + ((quad & 2) << 2)) * PITCH + ((quad & 1) << 4);

    for (int c = 0; c < 2; c++) {
        // ---- stage A chunk [128 x 64] --------------------------------------
        {
            int r = tid >> 1, half = tid & 1;
            int gr = row0 + r;
            if (HALF_IN) {
                const uint4* ip = reinterpret_cast<const uint4*>(
                    (const __half*)in_ + (size_t)gr * CIN + c * 64 + half * 32);
                uint4* ar = reinterpret_cast<uint4*>(A0 + r * PITCH + half * 64);
                if (gr < NN) {
#pragma unroll
                    for (int q = 0; q < 4; q++) ar[q] = ip[q];
                } else {
                    uint4 z = make_uint4(0, 0, 0, 0);
#pragma unroll
                    for (int q = 0; q < 4; q++) ar[q] = z;
                }
            } else {
                const float* ip = (const float*)in_ + (size_t)gr * CIN + c * 64 + half * 32;
                __half2* ar = reinterpret_cast<__half2*>(A0 + r * PITCH + half * 64);
#pragma unroll
                for (int q = 0; q < 8; q++) {
                    float4 v = make_float4(0.f, 0.f, 0.f, 0.f);
                    if (gr < NN) v = *reinterpret_cast<const float4*>(ip + q * 4);
                    ar[q * 2]     = __floats2half2_rn(v.x, v.y);
                    ar[q * 2 + 1] = __floats2half2_rn(v.z, v.w);
                }
            }
        }
        // ---- stage B chunk [COUT x 64] fp16 copy ---------------------------
        {
            constexpr int TPR = 256 / COUT;
            constexpr int VPT = 8 / TPR;
            int n = tid / TPR, part = tid % TPR;
            const uint4* sh = reinterpret_cast<const uint4*>(wh + n * 128 + c * 64) + part * VPT;
            const uint4* sl = reinterpret_cast<const uint4*>(wl + n * 128 + c * 64) + part * VPT;
            uint4* dh = reinterpret_cast<uint4*>(Bh + n * PITCH) + part * VPT;
            uint4* dl = reinterpret_cast<uint4*>(Bl + n * PITCH) + part * VPT;
#pragma unroll
            for (int v = 0; v < VPT; v++) { dh[v] = sh[v]; dl[v] = sl[v]; }
        }
        __syncthreads();

        // ---- compute: 4 k16 steps, 2 MMAs per n8-pair ----------------------
#pragma unroll
        for (int kk = 0; kk < 4; kk++) {
            uint32_t ka = (uint32_t)(kk << 5);
            uint32_t afr[2][4];
            ldsm4(afr[0], aoff + ka);
            ldsm4(afr[1], aoff + 16 * PITCH + ka);
#pragma unroll
            for (int tp = 0; tp < NTW / 2; tp++) {
                uint32_t bfr[4], bfl[4];
                ldsm4(bfr, boff + tp * 16 * PITCH + ka);
                ldsm4(bfl, boff + BSZ + tp * 16 * PITCH + ka);
#pragma unroll
                for (int f = 0; f < 2; f++) {
                    mma16816(acc[f][2 * tp],     afr[f], bfr[0], bfr[1]);
                    mma16816(acc[f][2 * tp],     afr[f], bfl[0], bfl[1]);
                    mma16816(acc[f][2 * tp + 1], afr[f], bfr[2], bfr[3]);
                    mma16816(acc[f][2 * tp + 1], afr[f], bfl[2], bfl[3]);
                }
            }
        }
        __syncthreads();
    }

    // ---- epilogue -----------------------------------------------------------
#pragma unroll
    for (int f = 0; f < 2; f++) {
        int r0g = row0 + wm * 32 + f * 16 + (lane >> 2);
        float ds0 = 1.f, ds1 = 1.f;
        if (HALF_IN) {
            ds0 = (r0g < NN) ? g_dis[r0g] : 0.f;
            ds1 = (r0g + 8 < NN) ? g_dis[r0g + 8] : 0.f;
        }
#pragma unroll
        for (int t = 0; t < NTW; t++) {
            int ncol = wn * (COUT / 2) + t * 8 + ((lane & 3) << 1);
            if (r0g < NN) {
                __half2 o = __floats2half2_rn(acc[f][t][0] * ds0, acc[f][t][1] * ds0);
                *reinterpret_cast<__half2*>(h + (size_t)r0g * COUT + ncol) = o;
            }
            if (r0g + 8 < NN) {
                __half2 o = __floats2half2_rn(acc[f][t][2] * ds1, acc[f][t][3] * ds1);
                *reinterpret_cast<__half2*>(h + (size_t)(r0g + 8) * COUT + ncol) = o;
            }
        }
    }
}

// --------- gather (layers 1,2): nxt = fp16(relu(dd*(Σ h'[s] + h'[d]) + b)) ---
__global__ void k_gather128(const __half* __restrict__ h, const float* __restrict__ bias,
                            __half* __restrict__ nxt)
{
    int warp = (blockIdx.x * blockDim.x + threadIdx.x) >> 5;
    int lane = threadIdx.x & 31;
    if (warp >= NN) return;
    int beg = g_off[warp], end = g_off[warp + 1];
    const uint2* hp = reinterpret_cast<const uint2*>(h);
    float4 acc = h4_to_f4(hp[warp * 32 + lane]);       // self term
    int i = beg;
    for (; i + 4 <= end; i += 4) {
        float4 v0 = h4_to_f4(hp[g_ep[i    ] * 32 + lane]);
        float4 v1 = h4_to_f4(hp[g_ep[i + 1] * 32 + lane]);
        float4 v2 = h4_to_f4(hp[g_ep[i + 2] * 32 + lane]);
        float4 v3 = h4_to_f4(hp[g_ep[i + 3] * 32 + lane]);
        acc.x += (v0.x + v1.x) + (v2.x + v3.x);
        acc.y += (v0.y + v1.y) + (v2.y + v3.y);
        acc.z += (v0.z + v1.z) + (v2.z + v3.z);
        acc.w += (v0.w + v1.w) + (v2.w + v3.w);
    }
    for (; i < end; i++) {
        float4 v = h4_to_f4(hp[g_ep[i] * 32 + lane]);
        acc.x += v.x; acc.y += v.y; acc.z += v.z; acc.w += v.w;
    }
    float dd = g_dis[warp];
    float4 b = reinterpret_cast<const float4*>(bias)[lane];
    float rx = fmaxf(fmaf(acc.x, dd, b.x), 0.f);
    float ry = fmaxf(fmaf(acc.y, dd, b.y), 0.f);
    float rz = fmaxf(fmaf(acc.z, dd, b.z), 0.f);
    float rw = fmaxf(fmaf(acc.w, dd, b.w), 0.f);
    uint2 o;
    __half2 o0 = __floats2half2_rn(rx, ry);
    __half2 o1 = __floats2half2_rn(rz, rw);
    o.x = *reinterpret_cast<uint32_t*>(&o0);
    o.y = *reinterpret_cast<uint32_t*>(&o1);
    reinterpret_cast<uint2*>(nxt)[warp * 32 + lane] = o;
}

// final layer: COUT=64, fused +b3, fp32 straight to out
__global__ void k_gather64f(const __half* __restrict__ h, const float* __restrict__ b3,
                            float* __restrict__ out)
{
    int warp = (blockIdx.x * blockDim.x + threadIdx.x) >> 5;
    int lane = threadIdx.x & 31;
    if (warp >= NN) return;
    int beg = g_off[warp], end = g_off[warp + 1];
    const uint32_t* hp = reinterpret_cast<const uint32_t*>(h);
    uint32_t su = hp[warp * 32 + lane];
    float2 acc = __half22float2(*reinterpret_cast<__half2*>(&su));  // self term
    int i = beg;
    for (; i + 4 <= end; i += 4) {
        uint32_t u0 = hp[g_ep[i    ] * 32 + lane];
        uint32_t u1 = hp[g_ep[i + 1] * 32 + lane];
        uint32_t u2 = hp[g_ep[i + 2] * 32 + lane];
        uint32_t u3 = hp[g_ep[i + 3] * 32 + lane];
        float2 v0 = __half22float2(*reinterpret_cast<__half2*>(&u0));
        float2 v1 = __half22float2(*reinterpret_cast<__half2*>(&u1));
        float2 v2 = __half22float2(*reinterpret_cast<__half2*>(&u2));
        float2 v3 = __half22float2(*reinterpret_cast<__half2*>(&u3));
        acc.x += (v0.x + v1.x) + (v2.x + v3.x);
        acc.y += (v0.y + v1.y) + (v2.y + v3.y);
    }
    for (; i < end; i++) {
        uint32_t u = hp[g_ep[i] * 32 + lane];
        float2 v = __half22float2(*reinterpret_cast<__half2*>(&u));
        acc.x += v.x; acc.y += v.y;
    }
    float dd = g_dis[warp];
    float2 b = reinterpret_cast<const float2*>(b3)[lane];
    float2 r;
    r.x = fmaf(acc.x, dd, b.x);
    r.y = fmaf(acc.y, dd, b.y);
    reinterpret_cast<float2*>(out)[warp * 32 + lane] = r;
}

// ---------------- launcher ---------------------------------------------------
extern "C" void kernel_launch(void* const* d_in, const int* in_sizes, int n_in,
                              void* d_out, int out_size)
{
    const float* x  = (const float*)d_in[0];
    const int*   ei = (const int*)d_in[1];
    const float* W1 = (const float*)d_in[2];
    const float* b1 = (const float*)d_in[3];
    const float* W2 = (const float*)d_in[4];
    const float* b2 = (const float*)d_in[5];
    const float* W3 = (const float*)d_in[6];
    const float* b3 = (const float*)d_in[7];
    float* out = (float*)d_out;

    const int* src = ei;            // edge_index[0]
    const int* dst = ei + NE;       // edge_index[1]

    __half *ph = nullptr, *pa = nullptr;
    cudaGetSymbolAddress((void**)&ph, g_h);
    cudaGetSymbolAddress((void**)&pa, g_a);
    __half *w1h, *w1l, *w2h, *w2l, *w3h, *w3l;
    cudaGetSymbolAddress((void**)&w1h, g_w1h);
    cudaGetSymbolAddress((void**)&w1l, g_w1l);
    cudaGetSymbolAddress((void**)&w2h, g_w2h);
    cudaGetSymbolAddress((void**)&w2l, g_w2l);
    cudaGetSymbolAddress((void**)&w3h, g_w3h);
    cudaGetSymbolAddress((void**)&w3l, g_w3l);

    const int smemL1 = 1 * 128 * 144 + 2 * 128 * 144;   // 55296 (single fp16 A)
    const int smemL2 = 1 * 128 * 144 + 2 * 128 * 144;   // 55296
    const int smemL3 = 1 * 128 * 144 + 2 * 64 * 144;    // 36864
    cudaFuncSetAttribute(k_gemm_mma<128, false>, cudaFuncAttributeMaxDynamicSharedMemorySize, smemL1);
    cudaFuncSetAttribute(k_gemm_mma<128, true>,  cudaFuncAttributeMaxDynamicSharedMemorySize, smemL2);
    cudaFuncSetAttribute(k_gemm_mma<64,  true>,  cudaFuncAttributeMaxDynamicSharedMemorySize, smemL3);

    const int gB = (NN + 127) / 128;         // 782 M-tiles
    const int gG = (NN * 32 + 255) / 256;    // warp per node

    // fork machinery (host objects only; safe during stream capture)
    cudaStream_t s2;
    cudaStreamCreateWithFlags(&s2, cudaStreamNonBlocking);
    cudaEvent_t eFork, eDis, eJoin;
    cudaEventCreateWithFlags(&eFork, cudaEventDisableTiming);
    cudaEventCreateWithFlags(&eDis,  cudaEventDisableTiming);
    cudaEventCreateWithFlags(&eJoin, cudaEventDisableTiming);

    // ---- setup root ----
    k_init<<<NBLK, 256>>>(W1, W2, W3);
    cudaEventRecord(eFork, 0);

    // ---- branch A (side stream): layer-1 GEMM (weights only) ----
    cudaStreamWaitEvent(s2, eFork, 0);
    k_gemm_mma<128, false><<<gB, 256, smemL1, s2>>>(x, w1h, w1l, ph);

    // ---- branch B (main stream): degree + dis ----
    k_deg_count<<<(NE + 255) / 256, 256>>>(dst);
    k_scan1<<<NBLK, 256>>>();
    cudaEventRecord(eDis, 0);                       // dis ready

    // side stream: scale h1 by dis (hidden under scan2..fill)
    cudaStreamWaitEvent(s2, eDis, 0);
    k_scale<<<(NN * 32 + 255) / 256, 256, 0, s2>>>();
    cudaEventRecord(eJoin, s2);

    // main stream: finish CSR
    k_scan2<<<1, 512>>>();
    k_scan3<<<NBLK, 256>>>();
    k_fill<<<(NE + 255) / 256, 256>>>(src, dst);

    // ---- join, then serial layer chain (R12 topology) ----
    cudaStreamWaitEvent(0, eJoin, 0);
    k_gather128<<<gG, 256>>>(ph, b1, pa);
    k_gemm_mma<128, true><<<gB, 256, smemL2>>>(pa, w2h, w2l, ph);
    k_gather128<<<gG, 256>>>(ph, b2, pa);
    k_gemm_mma<64, true><<<gB, 256, smemL3>>>(pa, w3h, w3l, ph);
    k_gather64f<<<gG, 256>>>(ph, b3, out);
    // streams/events intentionally not destroyed (host objects; capture-safe)
}